// round 17
// baseline (speedup 1.0000x reference)
#include <cuda_runtime.h>
#include <cstdint>

#define THREADS 256
#define KDIM 120
#define INP 512
#define NPAIR 13
#define KC 24
#define NCHUNK 5
#define NJ2 12
#define X_STRIDE 1028     // proven conflict-free layout (117/109.5us kernels)

// dynamic smem float offsets (W lives in constant memory)
#define SX_FLOATS (NJ2 * X_STRIDE)           // 12336
#define SCR_STRIDE 27                        // scratch aliases sX (256*27=6912 < 12336)
#define RED_OFF SX_FLOATS                    // [8][26]
#define RAW_OFF (RED_OFF + 8 * 26)
#define OUT_OFF (RAW_OFF + 32)
#define SMEM_FLOATS (OUT_OFF + 32)           // 12608
#define SMEM_BYTES (SMEM_FLOATS * 4)         // 50432

typedef unsigned long long ull;

// W packed [120][26] floats (col 25 = 0): viewed as 780 ulonglong2.
// j2-block g: cW2[g*13+q]; q=0..5: k0 pairs (2q,2q+1); q=6: {k0 pair12, k1 pair0};
// q=7..12: k1 pairs (2q-13, 2q-12).
__constant__ ulonglong2 cW2[780];   // zero-initialized; pad lanes never written

__device__ __forceinline__ ull dup2(float v) {
    ull r;
    asm("mov.b64 %0, {%1, %1};" : "=l"(r) : "r"(__float_as_uint(v)));
    return r;
}
__device__ __forceinline__ void ffma2(ull& d, ull a, ull b) {
    asm("fma.rn.f32x2 %0, %1, %2, %0;" : "+l"(d) : "l"(a), "l"(b));
}
__device__ __forceinline__ void unpack2(ull v, float& lo, float& hi) {
    unsigned int a, b2;
    asm("mov.b64 {%0, %1}, %2;" : "=r"(a), "=r"(b2) : "l"(v));
    lo = __uint_as_float(a);
    hi = __uint_as_float(b2);
}

extern __shared__ float smem[];

__global__ void __launch_bounds__(THREADS, 3)   // <- 3 CTAs/SM (85-reg cap)
caps_kernel(const float* __restrict__ x, float* __restrict__ out)
{
    const int b = blockIdx.x;
    const int t = threadIdx.x;
    const int lane = t & 31, g = t >> 5;

    float* sX      = smem;                 // [NJ2][X_STRIDE]
    float* scratch = smem;                 // routing partials alias sX
    float* red     = smem + RED_OFF;       // [8][26]
    float* raw     = smem + RAW_OFF;       // [25]
    float* sOut    = smem + OUT_OFF;       // [25]

    // ---- GEMM: u_hat[2 rows][26 cols] in 26 f32x2 accumulators, W from constant ----
    ull acc[2][NPAIR];
    #pragma unroll
    for (int r = 0; r < 2; r++)
        #pragma unroll
        for (int p = 0; p < NPAIR; p++) acc[r][p] = 0ull;

    const float4* xg = reinterpret_cast<const float4*>(x) + (size_t)b * (INP * KDIM / 4);

    for (int kc = 0; kc < NCHUNK; kc++) {
        __syncthreads();                 // sX safe to overwrite
        const int k0q = kc * (KC / 4);
        #pragma unroll
        for (int it2 = 0; it2 < (INP * (KC / 4)) / THREADS; it2++) {   // 12 float4/thread
            int idx  = t + it2 * THREADS;
            int row  = idx / (KC / 4);
            int slot = idx % (KC / 4);
            float4 v = xg[row * (KDIM / 4) + k0q + slot];
            float* p0 = sX + (2 * slot) * X_STRIDE + (row >> 1) * 4 + (row & 1) * 2;
            *reinterpret_cast<float2*>(p0)            = make_float2(v.x, v.y);  // j2 = 2*slot
            *reinterpret_cast<float2*>(p0 + X_STRIDE) = make_float2(v.z, v.w);  // j2 = 2*slot+1
        }
        __syncthreads();

        const ulonglong2* wb = cW2 + kc * NJ2 * NPAIR;
        #pragma unroll
        for (int j2 = 0; j2 < NJ2; j2++) {
            // {x(k0,r0), x(k1,r0), x(k0,r1), x(k1,r1)}
            float4 xv = *reinterpret_cast<const float4*>(sX + j2 * X_STRIDE + t * 4);
            ull a0 = dup2(xv.x);   // k0, row0
            ull a1 = dup2(xv.y);   // k1, row0
            ull b0 = dup2(xv.z);   // k0, row1
            ull b1 = dup2(xv.w);   // k1, row1

            const ulonglong2* wq = wb + j2 * NPAIR;
            // q = 0..5 : k0 pairs (2q, 2q+1)
            #pragma unroll
            for (int q = 0; q < 6; q++) {
                ulonglong2 v = wq[q];
                ffma2(acc[0][2 * q],     a0, v.x);
                ffma2(acc[1][2 * q],     b0, v.x);
                ffma2(acc[0][2 * q + 1], a0, v.y);
                ffma2(acc[1][2 * q + 1], b0, v.y);
            }
            // q = 6 : k0 pair 12, k1 pair 0
            {
                ulonglong2 v = wq[6];
                ffma2(acc[0][12], a0, v.x);
                ffma2(acc[1][12], b0, v.x);
                ffma2(acc[0][0],  a1, v.y);
                ffma2(acc[1][0],  b1, v.y);
            }
            // q = 7..12 : k1 pairs (2q-13, 2q-12)
            #pragma unroll
            for (int q = 7; q < 13; q++) {
                ulonglong2 v = wq[q];
                ffma2(acc[0][2 * q - 13], a1, v.x);
                ffma2(acc[1][2 * q - 13], b1, v.x);
                ffma2(acc[0][2 * q - 12], a1, v.y);
                ffma2(acc[1][2 * q - 12], b1, v.y);
            }
        }
    }
    __syncthreads();

    // ---- unpack u_hat ----
    float u[2][26];
    #pragma unroll
    for (int r = 0; r < 2; r++)
        #pragma unroll
        for (int p = 0; p < NPAIR; p++)
            unpack2(acc[r][p], u[r][2 * p], u[r][2 * p + 1]);

    float bb[2][5];
    #pragma unroll
    for (int r = 0; r < 2; r++)
        #pragma unroll
        for (int i = 0; i < 5; i++) bb[r][i] = 0.f;

    // ---- 4 routing iterations (verbatim from validated kernel) ----
    for (int it = 0; it < 4; it++) {
        float cw[2][5];
        #pragma unroll
        for (int r = 0; r < 2; r++) {
            float m = bb[r][0];
            #pragma unroll
            for (int i = 1; i < 5; i++) m = fmaxf(m, bb[r][i]);
            float e[5], s = 0.f;
            #pragma unroll
            for (int i = 0; i < 5; i++) { e[i] = __expf(bb[r][i] - m); s += e[i]; }
            float inv = 1.f / s;
            #pragma unroll
            for (int i = 0; i < 5; i++) cw[r][i] = e[i] * inv;
        }
        #pragma unroll
        for (int c = 0; c < 25; c++)
            scratch[t * SCR_STRIDE + c] = cw[0][c / 5] * u[0][c] + cw[1][c / 5] * u[1][c];
        __syncthreads();
        if (lane < 25) {
            float s = 0.f;
            #pragma unroll
            for (int uu = 0; uu < 32; uu++) s += scratch[(g * 32 + uu) * SCR_STRIDE + lane];
            red[g * 26 + lane] = s;
        }
        __syncthreads();
        if (t < 25) {
            float s = 0.f;
            #pragma unroll
            for (int gg = 0; gg < 8; gg++) s += red[gg * 26 + t];
            raw[t] = s;
        }
        __syncthreads();
        if (t < 25) {
            int i5 = (t / 5) * 5;
            float sq = 0.f;
            #pragma unroll
            for (int k = 0; k < 5; k++) { float v = raw[i5 + k]; sq += v * v; }
            sOut[t] = raw[t] * rsqrtf(sq + 1e-7f);   // squash = pure norm-normalization
        }
        __syncthreads();
        if (it < 3) {
            float ov[25];
            #pragma unroll
            for (int c = 0; c < 25; c++) ov[c] = sOut[c];
            #pragma unroll
            for (int r = 0; r < 2; r++)
                #pragma unroll
                for (int i = 0; i < 5; i++) {
                    float s = 0.f;
                    #pragma unroll
                    for (int k = 0; k < 5; k++) s += ov[i * 5 + k] * u[r][i * 5 + k];
                    bb[r][i] = s;   // b REPLACED each iteration (matches reference)
                }
        }
    }

    if (t < 25) out[b * 25 + t] = sOut[t];
}

extern "C" void kernel_launch(void* const* d_in, const int* in_sizes, int n_in,
                              void* d_out, int out_size)
{
    const float* x = (const float*)d_in[0];
    const float* W = (const float*)d_in[1];
    float* out = (float*)d_out;

    // Pack W[120][25] -> constant [120][26] floats (col 25 stays 0 from static init).
    void* csym = nullptr;
    cudaGetSymbolAddress(&csym, cW2);
    cudaMemcpy2DAsync(csym, 26 * sizeof(float),
                      W, 25 * sizeof(float),
                      25 * sizeof(float), KDIM,
                      cudaMemcpyDeviceToDevice, 0);

    cudaFuncSetAttribute(caps_kernel, cudaFuncAttributeMaxDynamicSharedMemorySize, SMEM_BYTES);
    caps_kernel<<<1024, THREADS, SMEM_BYTES>>>(x, out);
}